// round 12
// baseline (speedup 1.0000x reference)
#include <cuda_runtime.h>
#include <math.h>

// ---------------- problem constants (fixed shapes) ----------------
#define B_      2
#define N_      6
#define CAMS    (B_ * N_)          // 12
#define CAM_C   256
#define OUT_C   64
#define D_BINS  59
#define M_FEAT  (D_BINS + OUT_C)   // 123
#define FH      16
#define FW      44
#define HW      (FH * FW)          // 704
#define NX      128
#define NY      128
#define NCELL   (NX * NY)          // 16384 (NZ = 1)

// tile: 2 image columns x 16 rows = 32 pixels. np = wl*16 + h
#define WCOLS   2
#define BM 128
#define BN 32
#define BK 32
#define NCHUNK (CAM_C / BK)              // 8
#define NTHREADS 256
#define NBLOCKS  ((FW / WCOLS) * CAMS)   // 264 (<= 148*2: all co-resident @occ 2)

#define WS_STRIDE 130
#define XS_STRIDE 36
#define DS_STRIDE 61
#define CS_STRIDE 68

#define SMEM_FLOATS (BK * WS_STRIDE + BK * XS_STRIDE)   // 5312 (covers all phases)

#define SCR_SZ (B_ * NCELL * OUT_C)   // 2M floats = 8 MB
#define NTILES (B_ * NCELL / 64)      // 512 transpose tiles of 64 cells

typedef unsigned long long ull;

// scratch BEV accumulator, channel-contiguous: (B, cell, OUT_C).
// Zero at module load; the transpose phase restores zeros as it reads,
// so scratch is zero at every kernel entry (graph replays included).
__device__ float g_scratch[SCR_SZ];
// monotonic ticket counter (never reset; ticket math handles graph replays)
__device__ int g_cnt_scat;

// ------- single fused kernel: GEMM + softmax + scatter + transpose ---------
__global__ __launch_bounds__(NTHREADS, 2)
void lss_fused_kernel(const float* __restrict__ x,
                      const float* __restrict__ rots,
                      const float* __restrict__ trans,
                      const float* __restrict__ intrins,
                      const float* __restrict__ depth_w,
                      const float* __restrict__ depth_b,
                      float* __restrict__ out)
{
    __shared__ __align__(16) float smem[SMEM_FLOATS];
    __shared__ float comb[9];
    __shared__ float tr[3];
    __shared__ int   s_fast;
    __shared__ int   s_tgt1;

    float* Ws = smem;                       // [kk][m], stride 130
    float* Xs = smem + BK * WS_STRIDE;      // [kk][np], stride 36

    const int cam = blockIdx.y;             // 0..11
    const int b   = cam / N_;
    const int w0  = blockIdx.x * WCOLS;     // image-column pair start
    const int tid = threadIdx.x;
    const int tm  = tid >> 3;               // 0..31 -> 4 M-rows (2 even pairs)
    const int tn  = tid & 7;                // 0..7  -> 4 pixels
    const int bid = blockIdx.y * gridDim.x + blockIdx.x;

    // --- geometry setup: comb = rots @ inv(K) (thread 0) ---
    if (tid == 0) {
        const float* R = rots    + cam * 9;
        const float* K = intrins + cam * 9;
        float a = K[0], bb = K[1], c = K[2];
        float d = K[3], e  = K[4], f = K[5];
        float g = K[6], h  = K[7], i = K[8];
        float A  = e * i - f * h;
        float Bv = -(d * i - f * g);
        float Cv = d * h - e * g;
        float id = 1.0f / (a * A + bb * Bv + c * Cv);
        float inv[9];
        inv[0] = A * id;  inv[1] = (c * h - bb * i) * id; inv[2] = (bb * f - c * e) * id;
        inv[3] = Bv * id; inv[4] = (a * i - c * g) * id;  inv[5] = (c * d - a * f) * id;
        inv[6] = Cv * id; inv[7] = (bb * g - a * h) * id; inv[8] = (a * e - bb * d) * id;
        #pragma unroll
        for (int r = 0; r < 3; r++)
            #pragma unroll
            for (int col = 0; col < 3; col++)
                comb[r * 3 + col] = R[r * 3 + 0] * inv[0 + col]
                                  + R[r * 3 + 1] * inv[3 + col]
                                  + R[r * 3 + 2] * inv[6 + col];
        tr[0] = trans[cam * 3 + 0];
        tr[1] = trans[cam * 3 + 1];
        tr[2] = trans[cam * 3 + 2];
        // fast path: gx, gy independent of image row (exact zeros)
        s_fast = (comb[1] == 0.0f) && (comb[4] == 0.0f);
    }

    // --- phase 1: feat = W @ x, FFMA2, register-prefetched chunks ---
    ull acc[2][4];                           // [M-pair][pixel]
    #pragma unroll
    for (int i4 = 0; i4 < 2; i4++)
        #pragma unroll
        for (int j = 0; j < 4; j++) acc[i4][j] = 0ull;

    const float* xcam = x + (size_t)cam * CAM_C * HW;

    float wreg[16];   // BM*BK/NTHREADS
    float xreg[4];    // BK*BN/NTHREADS

    // prologue: load chunk 0 into registers
    #pragma unroll
    for (int it = 0; it < 16; it++) {
        int idx = it * NTHREADS + tid;
        int m   = idx >> 5;
        int kk  = idx & 31;
        wreg[it] = (m < M_FEAT) ? depth_w[m * CAM_C + kk] : 0.f;
    }
    #pragma unroll
    for (int it = 0; it < 4; it++) {
        int idx = it * NTHREADS + tid;
        int kk  = idx >> 5;
        int sub = idx & 31;
        int wl  = sub & 1;
        int h   = sub >> 1;
        xreg[it] = xcam[(size_t)kk * HW + h * FW + w0 + wl];
    }

    for (int c = 0; c < NCHUNK; c++) {
        // publish prefetched chunk c to smem
        #pragma unroll
        for (int it = 0; it < 16; it++) {
            int idx = it * NTHREADS + tid;
            int m   = idx >> 5;
            int kk  = idx & 31;
            Ws[kk * WS_STRIDE + m] = wreg[it];
        }
        #pragma unroll
        for (int it = 0; it < 4; it++) {
            int idx = it * NTHREADS + tid;
            int kk  = idx >> 5;
            int sub = idx & 31;
            int wl  = sub & 1;
            int h   = sub >> 1;
            Xs[kk * XS_STRIDE + wl * 16 + h] = xreg[it];
        }
        __syncthreads();

        // prefetch chunk c+1 into registers (latency hidden by compute below)
        if (c + 1 < NCHUNK) {
            int kc = (c + 1) * BK;
            #pragma unroll
            for (int it = 0; it < 16; it++) {
                int idx = it * NTHREADS + tid;
                int m   = idx >> 5;
                int kk  = idx & 31;
                wreg[it] = (m < M_FEAT) ? depth_w[m * CAM_C + kc + kk] : 0.f;
            }
            #pragma unroll
            for (int it = 0; it < 4; it++) {
                int idx = it * NTHREADS + tid;
                int kk  = idx >> 5;
                int sub = idx & 31;
                int wl  = sub & 1;
                int h   = sub >> 1;
                xreg[it] = xcam[(size_t)(kc + kk) * HW + h * FW + w0 + wl];
            }
        }

        // compute chunk c: 2 LDS.64 (W) + 1 LDS.128 (X) per kk
        #pragma unroll 4
        for (int kk = 0; kk < BK; kk++) {
            ull wp[2];
            #pragma unroll
            for (int i4 = 0; i4 < 2; i4++)
                wp[i4] = *(const ull*)&Ws[kk * WS_STRIDE + tm * 4 + 2 * i4];
            float4 xv = *(const float4*)&Xs[kk * XS_STRIDE + tn * 4];
            ull xd[4];
            asm("mov.b64 %0, {%1, %1};" : "=l"(xd[0]) : "f"(xv.x));
            asm("mov.b64 %0, {%1, %1};" : "=l"(xd[1]) : "f"(xv.y));
            asm("mov.b64 %0, {%1, %1};" : "=l"(xd[2]) : "f"(xv.z));
            asm("mov.b64 %0, {%1, %1};" : "=l"(xd[3]) : "f"(xv.w));
            #pragma unroll
            for (int i4 = 0; i4 < 2; i4++)
                #pragma unroll
                for (int j = 0; j < 4; j++)
                    asm("fma.rn.f32x2 %0, %1, %2, %0;"
                        : "+l"(acc[i4][j]) : "l"(wp[i4]), "l"(xd[j]));
        }
        __syncthreads();
    }

    // --- phase 2: unpack accs (+bias) into depthS / ctxS ---
    float* depthS = smem;                     // [np][61]
    float* ctxS   = smem + BN * DS_STRIDE;    // [np][68]

    #pragma unroll
    for (int i4 = 0; i4 < 2; i4++) {
        int m0 = tm * 4 + 2 * i4;
        float b0 = (m0     < M_FEAT) ? depth_b[m0]     : 0.f;
        float b1 = (m0 + 1 < M_FEAT) ? depth_b[m0 + 1] : 0.f;
        #pragma unroll
        for (int j = 0; j < 4; j++) {
            float lo, hi;
            asm("mov.b64 {%0, %1}, %2;" : "=f"(lo), "=f"(hi) : "l"(acc[i4][j]));
            int pix = tn * 4 + j;
            float v0 = lo + b0, v1 = hi + b1;
            if (m0 < D_BINS)       depthS[pix * DS_STRIDE + m0] = v0;
            else if (m0 < M_FEAT)  ctxS[pix * CS_STRIDE + (m0 - D_BINS)] = v0;
            int m1 = m0 + 1;
            if (m1 < D_BINS)       depthS[pix * DS_STRIDE + m1] = v1;
            else if (m1 < M_FEAT)  ctxS[pix * CS_STRIDE + (m1 - D_BINS)] = v1;
        }
    }
    __syncthreads();

    const float c00 = comb[0], c01 = comb[1], c02 = comb[2];
    const float c10 = comb[3], c11 = comb[4], c12 = comb[5];
    const float c20 = comb[6], c21 = comb[7], c22 = comb[8];
    const float t0 = tr[0], t1 = tr[1], t2 = tr[2];
    const float xstep = 703.0f / 43.0f;
    const float ystep = 255.0f / 15.0f;
    const int   fast  = s_fast;

    // --- softmax: 8 lanes per pixel, shfl reductions; zero z-invalid bins ---
    {
        int pix = tid >> 3;          // 0..31
        int sub = tid & 7;           // 0..7
        float* row = depthS + pix * DS_STRIDE;

        float mx = -1e30f;
        for (int d = sub; d < D_BINS; d += 8) mx = fmaxf(mx, row[d]);
        #pragma unroll
        for (int o = 1; o < 8; o <<= 1)
            mx = fmaxf(mx, __shfl_xor_sync(0xffffffffu, mx, o));

        float s = 0.f;
        for (int d = sub; d < D_BINS; d += 8) {
            float e = __expf(row[d] - mx);
            row[d] = e;
            s += e;
        }
        #pragma unroll
        for (int o = 1; o < 8; o <<= 1)
            s += __shfl_xor_sync(0xffffffffu, s, o);
        float invs = 1.0f / s;

        if (fast) {
            int wl = pix >> 4, h = pix & 15;
            float xim = (float)(w0 + wl) * xstep;
            float yim = (float)h * ystep;
            for (int d = sub; d < D_BINS; d += 8) {
                float ds = 1.0f + (float)d;
                float gz = c20 * (xim * ds) + c21 * (yim * ds) + c22 * ds + t2;
                int cz = (int)floorf((gz + 10.0f) / 20.0f);
                row[d] = (cz == 0) ? row[d] * invs : 0.f;
            }
        } else {
            for (int d = sub; d < D_BINS; d += 8) row[d] *= invs;
        }
    }
    __syncthreads();   // publish softmax; scratch is already zero (self-clean)

    float* base = g_scratch + (size_t)b * NCELL * OUT_C;

    if (fast) {
        // --- fast combine+scatter: warp = (wl, 16-depth chunk);
        //     lane = (dloc, channel-half). ctx broadcast, accs in registers.
        const int warp  = tid >> 5;           // 0..7
        const int lane  = tid & 31;
        const int wl    = warp & 1;
        const int d0    = (warp >> 1) * 16;   // 0,16,32,48
        const int dloc  = lane >> 1;          // 0..15
        const int d     = d0 + dloc;
        const int chalf = lane & 1;           // channels chalf*32 .. +31
        const bool dok  = (d < D_BINS);

        float ds  = 1.0f + (float)d;
        float xim = (float)(w0 + wl) * xstep;
        float gx = c00 * (xim * ds) + c02 * ds + t0;   // c01 exactly 0
        float gy = c10 * (xim * ds) + c12 * ds + t1;   // c11 exactly 0
        int cx = (int)floorf((gx + 51.2f) / 0.8f);
        int cy = (int)floorf((gy + 51.2f) / 0.8f);
        bool ok = dok && ((unsigned)cx < (unsigned)NX) && ((unsigned)cy < (unsigned)NY);

        ull v[16];                              // 8 float4 accumulators
        #pragma unroll
        for (int j = 0; j < 16; j++) v[j] = 0ull;
        float dwsum = 0.f;

        const float* drow0 = depthS + (wl * 16) * DS_STRIDE;
        const float* crow0 = ctxS   + (wl * 16) * CS_STRIDE + chalf * 32;

        #pragma unroll
        for (int h = 0; h < 16; h++) {
            float dw = dok ? drow0[h * DS_STRIDE + d] : 0.f;
            dwsum += dw;
            ull dw2; asm("mov.b64 %0, {%1, %1};" : "=l"(dw2) : "f"(dw));
            const float* cr = crow0 + h * CS_STRIDE;
            #pragma unroll
            for (int q = 0; q < 8; q++) {
                float4 cc = *(const float4*)(cr + q * 4);   // warp-broadcast
                ull lo, hi;
                asm("mov.b64 %0, {%1, %2};" : "=l"(lo) : "f"(cc.x), "f"(cc.y));
                asm("mov.b64 %0, {%1, %2};" : "=l"(hi) : "f"(cc.z), "f"(cc.w));
                asm("fma.rn.f32x2 %0, %1, %2, %0;" : "+l"(v[2*q  ]) : "l"(lo), "l"(dw2));
                asm("fma.rn.f32x2 %0, %1, %2, %0;" : "+l"(v[2*q+1]) : "l"(hi), "l"(dw2));
            }
        }

        if (ok && dwsum != 0.f) {
            float* dst = base + ((size_t)cy * NX + cx) * OUT_C + chalf * 32;
            #pragma unroll
            for (int q = 0; q < 8; q++) {
                float f0, f1, f2, f3;
                asm("mov.b64 {%0, %1}, %2;" : "=f"(f0), "=f"(f1) : "l"(v[2*q  ]));
                asm("mov.b64 {%0, %1}, %2;" : "=f"(f2), "=f"(f3) : "l"(v[2*q+1]));
                asm volatile("red.global.add.v4.f32 [%0], {%1, %2, %3, %4};"
                             :: "l"(dst + q * 4),
                                "f"(f0), "f"(f1), "f"(f2), "f"(f3) : "memory");
            }
        }
    } else {
        // --- generic fallback: per-point scatter (any geometry) ---
        for (int idx = tid; idx < BN * D_BINS; idx += NTHREADS) {
            int np = idx / D_BINS;
            int d  = idx - np * D_BINS;
            int wl = np >> 4, h = np & 15;
            float ds  = 1.0f + (float)d;
            float xim = (float)(w0 + wl) * xstep;
            float yim = (float)h * ystep;
            float px = xim * ds, py = yim * ds, pz = ds;
            float gx = c00 * px + c01 * py + c02 * pz + t0;
            float gy = c10 * px + c11 * py + c12 * pz + t1;
            float gz = c20 * px + c21 * py + c22 * pz + t2;
            int cx = (int)floorf((gx + 51.2f) / 0.8f);
            int cy = (int)floorf((gy + 51.2f) / 0.8f);
            int cz = (int)floorf((gz + 10.0f) / 20.0f);
            if (((unsigned)cx < (unsigned)NX) && ((unsigned)cy < (unsigned)NY) && cz == 0) {
                float dwgt = depthS[np * DS_STRIDE + d];
                float* dst = base + ((size_t)cy * NX + cx) * OUT_C;
                const float4* cv = (const float4*)(ctxS + np * CS_STRIDE);
                #pragma unroll
                for (int c4 = 0; c4 < OUT_C / 4; c4++) {
                    float4 v = cv[c4];
                    asm volatile("red.global.add.v4.f32 [%0], {%1, %2, %3, %4};"
                                 :: "l"(dst + c4 * 4),
                                    "f"(v.x * dwgt), "f"(v.y * dwgt),
                                    "f"(v.z * dwgt), "f"(v.w * dwgt) : "memory");
                }
            }
        }
    }

    // --- grid barrier: all reds posted & visible (volatile-load spin) ---
    __threadfence();
    if (tid == 0) {
        int t = atomicAdd(&g_cnt_scat, 1);
        s_tgt1 = t - (t % NBLOCKS) + NBLOCKS;
    }
    __syncthreads();
    if (tid == 0) {
        while (*(volatile int*)&g_cnt_scat < s_tgt1) __nanosleep(64);
    }
    __syncthreads();
    __threadfence();   // acquire: scratch reads below must not be hoisted

    // --- phase 4: transpose (B, cell, C) -> (B, C, cell) into d_out,
    //     restoring zeros to g_scratch as it reads (self-cleaning) ---
    {
        float (*tile)[65] = (float (*)[65])smem;   // 64 x 65 = 4160 floats, fits
        const float4 z4 = make_float4(0.f, 0.f, 0.f, 0.f);
        for (int t = bid; t < NTILES; t += NBLOCKS) {
            int bz    = t >> 8;             // t / 256
            int cell0 = (t & 255) * 64;
            __syncthreads();                // smem reuse across iterations
            #pragma unroll
            for (int i = 0; i < 4; i++) {
                int idx  = i * NTHREADS + tid;      // 0..1023
                int cell = idx >> 4;
                int c4   = idx & 15;
                float4* sp = (float4*)&g_scratch[
                    ((size_t)bz * NCELL + cell0 + cell) * OUT_C + c4 * 4];
                float4 v = *sp;
                *sp = z4;                           // restore zero for next run
                tile[c4 * 4 + 0][cell] = v.x;
                tile[c4 * 4 + 1][cell] = v.y;
                tile[c4 * 4 + 2][cell] = v.z;
                tile[c4 * 4 + 3][cell] = v.w;
            }
            __syncthreads();
            #pragma unroll
            for (int i = 0; i < 4; i++) {
                int idx = i * NTHREADS + tid;
                int ch  = idx >> 4;
                int seg = idx & 15;
                float4 v = make_float4(tile[ch][seg * 4 + 0], tile[ch][seg * 4 + 1],
                                       tile[ch][seg * 4 + 2], tile[ch][seg * 4 + 3]);
                *(float4*)&out[((size_t)(bz * OUT_C + ch)) * NCELL + cell0 + seg * 4] = v;
            }
        }
    }
}

// ---------------- launch ----------------
extern "C" void kernel_launch(void* const* d_in, const int* in_sizes, int n_in,
                              void* d_out, int out_size)
{
    const float* x       = (const float*)d_in[0];
    const float* rots    = (const float*)d_in[1];
    const float* trans   = (const float*)d_in[2];
    const float* intrins = (const float*)d_in[3];
    const float* depth_w = (const float*)d_in[4];
    const float* depth_b = (const float*)d_in[5];
    float* out = (float*)d_out;

    // single fused kernel: GEMM + softmax + scatter + transpose (self-clean)
    dim3 grid(FW / WCOLS, CAMS);   // (22, 12) = 264 blocks, occ 2 -> 1 wave
    lss_fused_kernel<<<grid, NTHREADS>>>(x, rots, trans, intrins,
                                         depth_w, depth_b, out);
    (void)in_sizes; (void)n_in; (void)out_size;
}

// round 13
// speedup vs baseline: 1.0977x; 1.0977x over previous
#include <cuda_runtime.h>
#include <math.h>

// ---------------- problem constants (fixed shapes) ----------------
#define B_      2
#define N_      6
#define CAMS    (B_ * N_)          // 12
#define CAM_C   256
#define OUT_C   64
#define D_BINS  59
#define M_FEAT  (D_BINS + OUT_C)   // 123
#define FH      16
#define FW      44
#define HW      (FH * FW)          // 704
#define NX      128
#define NY      128
#define NCELL   (NX * NY)          // 16384 (NZ = 1)

// tile: 2 image columns x 16 rows = 32 pixels. np = wl*16 + h
#define WCOLS   2
#define BM 128
#define BN 32
#define BK 32
#define NCHUNK (CAM_C / BK)              // 8
#define NTHREADS 256
#define NBLOCKS  ((FW / WCOLS) * CAMS)   // 264 (<= 148*2: all co-resident @occ 2)

#define WS_STRIDE 130
#define XS_STRIDE 36
#define DS_STRIDE 61
#define CS_STRIDE 68

#define SMEM_FLOATS (BK * WS_STRIDE + BK * XS_STRIDE)   // 5312 (covers all phases)

#define SCR_SZ (B_ * NCELL * OUT_C)   // 2M floats = 8 MB per buffer
#define NTILES (B_ * NCELL / 64)      // 512 transpose tiles of 64 cells

typedef unsigned long long ull;

// ping-pong scratch: buffer (ep&1) is active this launch (pre-zeroed by the
// previous launch); buffer (ep+1)&1 is zeroed during THIS launch, inside the
// barrier-2 window. Both zero at module load.
__device__ float g_scratch[2 * SCR_SZ];   // 16 MB
// monotonic ticket counter (never reset; ticket math handles graph replays)
__device__ int g_cnt_scat;
// launch epoch: read by all blocks at start, incremented once at the end
__device__ int g_epoch;

// ------- single fused kernel: GEMM + softmax + scatter + transpose ---------
__global__ __launch_bounds__(NTHREADS, 2)
void lss_fused_kernel(const float* __restrict__ x,
                      const float* __restrict__ rots,
                      const float* __restrict__ trans,
                      const float* __restrict__ intrins,
                      const float* __restrict__ depth_w,
                      const float* __restrict__ depth_b,
                      float* __restrict__ out)
{
    __shared__ __align__(16) float smem[SMEM_FLOATS];
    __shared__ float comb[9];
    __shared__ float tr[3];
    __shared__ int   s_fast;
    __shared__ int   s_ep;
    __shared__ int   s_tgt1;

    float* Ws = smem;                       // [kk][m], stride 130
    float* Xs = smem + BK * WS_STRIDE;      // [kk][np], stride 36

    const int cam = blockIdx.y;             // 0..11
    const int b   = cam / N_;
    const int w0  = blockIdx.x * WCOLS;     // image-column pair start
    const int tid = threadIdx.x;
    const int tm  = tid >> 3;               // 0..31 -> 4 M-rows (2 even pairs)
    const int tn  = tid & 7;                // 0..7  -> 4 pixels
    const int bid = blockIdx.y * gridDim.x + blockIdx.x;

    // --- epoch read + geometry setup (thread 0) ---
    if (tid == 0) {
        s_ep = *(volatile int*)&g_epoch;    // stable: writer runs post-barrier2

        const float* R = rots    + cam * 9;
        const float* K = intrins + cam * 9;
        float a = K[0], bb = K[1], c = K[2];
        float d = K[3], e  = K[4], f = K[5];
        float g = K[6], h  = K[7], i = K[8];
        float A  = e * i - f * h;
        float Bv = -(d * i - f * g);
        float Cv = d * h - e * g;
        float id = 1.0f / (a * A + bb * Bv + c * Cv);
        float inv[9];
        inv[0] = A * id;  inv[1] = (c * h - bb * i) * id; inv[2] = (bb * f - c * e) * id;
        inv[3] = Bv * id; inv[4] = (a * i - c * g) * id;  inv[5] = (c * d - a * f) * id;
        inv[6] = Cv * id; inv[7] = (bb * g - a * h) * id; inv[8] = (a * e - bb * d) * id;
        #pragma unroll
        for (int r = 0; r < 3; r++)
            #pragma unroll
            for (int col = 0; col < 3; col++)
                comb[r * 3 + col] = R[r * 3 + 0] * inv[0 + col]
                                  + R[r * 3 + 1] * inv[3 + col]
                                  + R[r * 3 + 2] * inv[6 + col];
        tr[0] = trans[cam * 3 + 0];
        tr[1] = trans[cam * 3 + 1];
        tr[2] = trans[cam * 3 + 2];
        // fast path: gx, gy independent of image row (exact zeros)
        s_fast = (comb[1] == 0.0f) && (comb[4] == 0.0f);
    }

    // --- phase 1: feat = W @ x, FFMA2, register-prefetched chunks ---
    ull acc[2][4];                           // [M-pair][pixel]
    #pragma unroll
    for (int i4 = 0; i4 < 2; i4++)
        #pragma unroll
        for (int j = 0; j < 4; j++) acc[i4][j] = 0ull;

    const float* xcam = x + (size_t)cam * CAM_C * HW;

    float wreg[16];   // BM*BK/NTHREADS
    float xreg[4];    // BK*BN/NTHREADS

    // prologue: load chunk 0 into registers
    #pragma unroll
    for (int it = 0; it < 16; it++) {
        int idx = it * NTHREADS + tid;
        int m   = idx >> 5;
        int kk  = idx & 31;
        wreg[it] = (m < M_FEAT) ? depth_w[m * CAM_C + kk] : 0.f;
    }
    #pragma unroll
    for (int it = 0; it < 4; it++) {
        int idx = it * NTHREADS + tid;
        int kk  = idx >> 5;
        int sub = idx & 31;
        int wl  = sub & 1;
        int h   = sub >> 1;
        xreg[it] = xcam[(size_t)kk * HW + h * FW + w0 + wl];
    }

    for (int c = 0; c < NCHUNK; c++) {
        // publish prefetched chunk c to smem
        #pragma unroll
        for (int it = 0; it < 16; it++) {
            int idx = it * NTHREADS + tid;
            int m   = idx >> 5;
            int kk  = idx & 31;
            Ws[kk * WS_STRIDE + m] = wreg[it];
        }
        #pragma unroll
        for (int it = 0; it < 4; it++) {
            int idx = it * NTHREADS + tid;
            int kk  = idx >> 5;
            int sub = idx & 31;
            int wl  = sub & 1;
            int h   = sub >> 1;
            Xs[kk * XS_STRIDE + wl * 16 + h] = xreg[it];
        }
        __syncthreads();

        // prefetch chunk c+1 into registers (latency hidden by compute below)
        if (c + 1 < NCHUNK) {
            int kc = (c + 1) * BK;
            #pragma unroll
            for (int it = 0; it < 16; it++) {
                int idx = it * NTHREADS + tid;
                int m   = idx >> 5;
                int kk  = idx & 31;
                wreg[it] = (m < M_FEAT) ? depth_w[m * CAM_C + kc + kk] : 0.f;
            }
            #pragma unroll
            for (int it = 0; it < 4; it++) {
                int idx = it * NTHREADS + tid;
                int kk  = idx >> 5;
                int sub = idx & 31;
                int wl  = sub & 1;
                int h   = sub >> 1;
                xreg[it] = xcam[(size_t)(kc + kk) * HW + h * FW + w0 + wl];
            }
        }

        // compute chunk c: 2 LDS.64 (W) + 1 LDS.128 (X) per kk
        #pragma unroll 4
        for (int kk = 0; kk < BK; kk++) {
            ull wp[2];
            #pragma unroll
            for (int i4 = 0; i4 < 2; i4++)
                wp[i4] = *(const ull*)&Ws[kk * WS_STRIDE + tm * 4 + 2 * i4];
            float4 xv = *(const float4*)&Xs[kk * XS_STRIDE + tn * 4];
            ull xd[4];
            asm("mov.b64 %0, {%1, %1};" : "=l"(xd[0]) : "f"(xv.x));
            asm("mov.b64 %0, {%1, %1};" : "=l"(xd[1]) : "f"(xv.y));
            asm("mov.b64 %0, {%1, %1};" : "=l"(xd[2]) : "f"(xv.z));
            asm("mov.b64 %0, {%1, %1};" : "=l"(xd[3]) : "f"(xv.w));
            #pragma unroll
            for (int i4 = 0; i4 < 2; i4++)
                #pragma unroll
                for (int j = 0; j < 4; j++)
                    asm("fma.rn.f32x2 %0, %1, %2, %0;"
                        : "+l"(acc[i4][j]) : "l"(wp[i4]), "l"(xd[j]));
        }
        __syncthreads();
    }

    // --- phase 2: unpack accs (+bias) into depthS / ctxS ---
    float* depthS = smem;                     // [np][61]
    float* ctxS   = smem + BN * DS_STRIDE;    // [np][68]

    #pragma unroll
    for (int i4 = 0; i4 < 2; i4++) {
        int m0 = tm * 4 + 2 * i4;
        float b0 = (m0     < M_FEAT) ? depth_b[m0]     : 0.f;
        float b1 = (m0 + 1 < M_FEAT) ? depth_b[m0 + 1] : 0.f;
        #pragma unroll
        for (int j = 0; j < 4; j++) {
            float lo, hi;
            asm("mov.b64 {%0, %1}, %2;" : "=f"(lo), "=f"(hi) : "l"(acc[i4][j]));
            int pix = tn * 4 + j;
            float v0 = lo + b0, v1 = hi + b1;
            if (m0 < D_BINS)       depthS[pix * DS_STRIDE + m0] = v0;
            else if (m0 < M_FEAT)  ctxS[pix * CS_STRIDE + (m0 - D_BINS)] = v0;
            int m1 = m0 + 1;
            if (m1 < D_BINS)       depthS[pix * DS_STRIDE + m1] = v1;
            else if (m1 < M_FEAT)  ctxS[pix * CS_STRIDE + (m1 - D_BINS)] = v1;
        }
    }
    __syncthreads();

    const float c00 = comb[0], c01 = comb[1], c02 = comb[2];
    const float c10 = comb[3], c11 = comb[4], c12 = comb[5];
    const float c20 = comb[6], c21 = comb[7], c22 = comb[8];
    const float t0 = tr[0], t1 = tr[1], t2 = tr[2];
    const float xstep = 703.0f / 43.0f;
    const float ystep = 255.0f / 15.0f;
    const int   fast  = s_fast;
    const int   ep    = s_ep;

    // --- softmax: 8 lanes per pixel, shfl reductions; zero z-invalid bins ---
    {
        int pix = tid >> 3;          // 0..31
        int sub = tid & 7;           // 0..7
        float* row = depthS + pix * DS_STRIDE;

        float mx = -1e30f;
        for (int d = sub; d < D_BINS; d += 8) mx = fmaxf(mx, row[d]);
        #pragma unroll
        for (int o = 1; o < 8; o <<= 1)
            mx = fmaxf(mx, __shfl_xor_sync(0xffffffffu, mx, o));

        float s = 0.f;
        for (int d = sub; d < D_BINS; d += 8) {
            float e = __expf(row[d] - mx);
            row[d] = e;
            s += e;
        }
        #pragma unroll
        for (int o = 1; o < 8; o <<= 1)
            s += __shfl_xor_sync(0xffffffffu, s, o);
        float invs = 1.0f / s;

        if (fast) {
            int wl = pix >> 4, h = pix & 15;
            float xim = (float)(w0 + wl) * xstep;
            float yim = (float)h * ystep;
            for (int d = sub; d < D_BINS; d += 8) {
                float ds = 1.0f + (float)d;
                float gz = c20 * (xim * ds) + c21 * (yim * ds) + c22 * ds + t2;
                int cz = (int)floorf((gz + 10.0f) / 20.0f);
                row[d] = (cz == 0) ? row[d] * invs : 0.f;
            }
        } else {
            for (int d = sub; d < D_BINS; d += 8) row[d] *= invs;
        }
    }
    __syncthreads();   // publish softmax; active buffer is pre-zeroed

    float* scrA = g_scratch + (size_t)(ep & 1) * SCR_SZ;          // active
    float* scrB = g_scratch + (size_t)((ep + 1) & 1) * SCR_SZ;    // to zero
    float* base = scrA + (size_t)b * NCELL * OUT_C;

    if (fast) {
        // --- fast combine+scatter: warp = (wl, 16-depth chunk);
        //     lane = (dloc, channel-half). ctx broadcast, accs in registers.
        const int warp  = tid >> 5;           // 0..7
        const int lane  = tid & 31;
        const int wl    = warp & 1;
        const int d0    = (warp >> 1) * 16;   // 0,16,32,48
        const int dloc  = lane >> 1;          // 0..15
        const int d     = d0 + dloc;
        const int chalf = lane & 1;           // channels chalf*32 .. +31
        const bool dok  = (d < D_BINS);

        float ds  = 1.0f + (float)d;
        float xim = (float)(w0 + wl) * xstep;
        float gx = c00 * (xim * ds) + c02 * ds + t0;   // c01 exactly 0
        float gy = c10 * (xim * ds) + c12 * ds + t1;   // c11 exactly 0
        int cx = (int)floorf((gx + 51.2f) / 0.8f);
        int cy = (int)floorf((gy + 51.2f) / 0.8f);
        bool ok = dok && ((unsigned)cx < (unsigned)NX) && ((unsigned)cy < (unsigned)NY);

        ull v[16];                              // 8 float4 accumulators
        #pragma unroll
        for (int j = 0; j < 16; j++) v[j] = 0ull;
        float dwsum = 0.f;

        const float* drow0 = depthS + (wl * 16) * DS_STRIDE;
        const float* crow0 = ctxS   + (wl * 16) * CS_STRIDE + chalf * 32;

        #pragma unroll
        for (int h = 0; h < 16; h++) {
            float dw = dok ? drow0[h * DS_STRIDE + d] : 0.f;
            dwsum += dw;
            ull dw2; asm("mov.b64 %0, {%1, %1};" : "=l"(dw2) : "f"(dw));
            const float* cr = crow0 + h * CS_STRIDE;
            #pragma unroll
            for (int q = 0; q < 8; q++) {
                float4 cc = *(const float4*)(cr + q * 4);   // warp-broadcast
                ull lo, hi;
                asm("mov.b64 %0, {%1, %2};" : "=l"(lo) : "f"(cc.x), "f"(cc.y));
                asm("mov.b64 %0, {%1, %2};" : "=l"(hi) : "f"(cc.z), "f"(cc.w));
                asm("fma.rn.f32x2 %0, %1, %2, %0;" : "+l"(v[2*q  ]) : "l"(lo), "l"(dw2));
                asm("fma.rn.f32x2 %0, %1, %2, %0;" : "+l"(v[2*q+1]) : "l"(hi), "l"(dw2));
            }
        }

        if (ok && dwsum != 0.f) {
            float* dst = base + ((size_t)cy * NX + cx) * OUT_C + chalf * 32;
            #pragma unroll
            for (int q = 0; q < 8; q++) {
                float f0, f1, f2, f3;
                asm("mov.b64 {%0, %1}, %2;" : "=f"(f0), "=f"(f1) : "l"(v[2*q  ]));
                asm("mov.b64 {%0, %1}, %2;" : "=f"(f2), "=f"(f3) : "l"(v[2*q+1]));
                asm volatile("red.global.add.v4.f32 [%0], {%1, %2, %3, %4};"
                             :: "l"(dst + q * 4),
                                "f"(f0), "f"(f1), "f"(f2), "f"(f3) : "memory");
            }
        }
    } else {
        // --- generic fallback: per-point scatter (any geometry) ---
        for (int idx = tid; idx < BN * D_BINS; idx += NTHREADS) {
            int np = idx / D_BINS;
            int d  = idx - np * D_BINS;
            int wl = np >> 4, h = np & 15;
            float ds  = 1.0f + (float)d;
            float xim = (float)(w0 + wl) * xstep;
            float yim = (float)h * ystep;
            float px = xim * ds, py = yim * ds, pz = ds;
            float gx = c00 * px + c01 * py + c02 * pz + t0;
            float gy = c10 * px + c11 * py + c12 * pz + t1;
            float gz = c20 * px + c21 * py + c22 * pz + t2;
            int cx = (int)floorf((gx + 51.2f) / 0.8f);
            int cy = (int)floorf((gy + 51.2f) / 0.8f);
            int cz = (int)floorf((gz + 10.0f) / 20.0f);
            if (((unsigned)cx < (unsigned)NX) && ((unsigned)cy < (unsigned)NY) && cz == 0) {
                float dwgt = depthS[np * DS_STRIDE + d];
                float* dst = base + ((size_t)cy * NX + cx) * OUT_C;
                const float4* cv = (const float4*)(ctxS + np * CS_STRIDE);
                #pragma unroll
                for (int c4 = 0; c4 < OUT_C / 4; c4++) {
                    float4 v = cv[c4];
                    asm volatile("red.global.add.v4.f32 [%0], {%1, %2, %3, %4};"
                                 :: "l"(dst + c4 * 4),
                                    "f"(v.x * dwgt), "f"(v.y * dwgt),
                                    "f"(v.z * dwgt), "f"(v.w * dwgt) : "memory");
                }
            }
        }
    }

    // --- grid barrier: take ticket, zero the OTHER buffer while waiting ---
    __threadfence();
    if (tid == 0) {
        int t = atomicAdd(&g_cnt_scat, 1);
        s_tgt1 = t - (t % NBLOCKS) + NBLOCKS;
    }
    __syncthreads();

    // zero next launch's buffer (cold lines, overlaps stragglers + red drain)
    {
        const int n4 = SCR_SZ / 4;                         // 524288 float4
        const int chunk = (n4 + NBLOCKS - 1) / NBLOCKS;
        int s = bid * chunk;
        int e = s + chunk; if (e > n4) e = n4;
        float4* p = (float4*)scrB;
        const float4 z4 = make_float4(0.f, 0.f, 0.f, 0.f);
        for (int i = s + tid; i < e; i += NTHREADS)
            p[i] = z4;
    }
    __syncthreads();

    if (tid == 0) {
        while (*(volatile int*)&g_cnt_scat < s_tgt1) __nanosleep(64);
    }
    __syncthreads();
    __threadfence();   // acquire: scratch reads below must not be hoisted

    // --- phase 4: transpose (B, cell, C) -> (B, C, cell), READ-ONLY ---
    {
        float (*tile)[65] = (float (*)[65])smem;   // 64 x 65 = 4160 floats, fits
        for (int t = bid; t < NTILES; t += NBLOCKS) {
            int bz    = t >> 8;             // t / 256
            int cell0 = (t & 255) * 64;
            __syncthreads();                // smem reuse across iterations
            #pragma unroll
            for (int i = 0; i < 4; i++) {
                int idx  = i * NTHREADS + tid;      // 0..1023
                int cell = idx >> 4;
                int c4   = idx & 15;
                float4 v = *(const float4*)&scrA[
                    ((size_t)bz * NCELL + cell0 + cell) * OUT_C + c4 * 4];
                tile[c4 * 4 + 0][cell] = v.x;
                tile[c4 * 4 + 1][cell] = v.y;
                tile[c4 * 4 + 2][cell] = v.z;
                tile[c4 * 4 + 3][cell] = v.w;
            }
            __syncthreads();
            #pragma unroll
            for (int i = 0; i < 4; i++) {
                int idx = i * NTHREADS + tid;
                int ch  = idx >> 4;
                int seg = idx & 15;
                float4 v = make_float4(tile[ch][seg * 4 + 0], tile[ch][seg * 4 + 1],
                                       tile[ch][seg * 4 + 2], tile[ch][seg * 4 + 3]);
                *(float4*)&out[((size_t)(bz * OUT_C + ch)) * NCELL + cell0 + seg * 4] = v;
            }
        }
    }

    // --- advance epoch (exactly one writer; all blocks have long since read) ---
    if (bid == 0 && tid == 0)
        *(volatile int*)&g_epoch = ep + 1;
}

// ---------------- launch ----------------
extern "C" void kernel_launch(void* const* d_in, const int* in_sizes, int n_in,
                              void* d_out, int out_size)
{
    const float* x       = (const float*)d_in[0];
    const float* rots    = (const float*)d_in[1];
    const float* trans   = (const float*)d_in[2];
    const float* intrins = (const float*)d_in[3];
    const float* depth_w = (const float*)d_in[4];
    const float* depth_b = (const float*)d_in[5];
    float* out = (float*)d_out;

    // single fused kernel: GEMM + softmax + scatter + transpose (ping-pong)
    dim3 grid(FW / WCOLS, CAMS);   // (22, 12) = 264 blocks, occ 2 -> 1 wave
    lss_fused_kernel<<<grid, NTHREADS>>>(x, rots, trans, intrins,
                                         depth_w, depth_b, out);
    (void)in_sizes; (void)n_in; (void)out_size;
}

// round 14
// speedup vs baseline: 1.1654x; 1.0617x over previous
#include <cuda_runtime.h>
#include <math.h>

// ---------------- problem constants (fixed shapes) ----------------
#define B_      2
#define N_      6
#define CAMS    (B_ * N_)          // 12
#define CAM_C   256
#define OUT_C   64
#define D_BINS  59
#define M_FEAT  (D_BINS + OUT_C)   // 123
#define FH      16
#define FW      44
#define HW      (FH * FW)          // 704
#define NX      128
#define NY      128
#define NCELL   (NX * NY)          // 16384 (NZ = 1)

// tile: 2 image columns x 16 rows = 32 pixels. np = wl*16 + h
#define WCOLS   2
#define BM 128
#define BN 32
#define BK 32
#define NCHUNK (CAM_C / BK)              // 8
#define NTHREADS 256
#define NBLOCKS  ((FW / WCOLS) * CAMS)   // 264 (<= 148*2: all co-resident @occ 2)

#define WS_STRIDE 130
#define XS_STRIDE 36
#define DS_STRIDE 61
#define CS_STRIDE 68

#define BUF_FLOATS (BK * WS_STRIDE + BK * XS_STRIDE)   // 5312 per buffer
#define SMEM_FLOATS (2 * BUF_FLOATS)                   // 10624 = 42.5 KB

#define SCR_SZ (B_ * NCELL * OUT_C)   // 2M floats = 8 MB per buffer
#define NTILES (B_ * NCELL / 64)      // 512 transpose tiles of 64 cells

typedef unsigned long long ull;

// ping-pong scratch: buffer (ep&1) is active this launch (pre-zeroed by the
// previous launch); buffer (ep+1)&1 is zeroed during THIS launch, inside the
// barrier window. Both zero at module load.
__device__ float g_scratch[2 * SCR_SZ];   // 16 MB
// monotonic ticket counter (never reset; ticket math handles graph replays)
__device__ int g_cnt_scat;
// launch epoch: read by all blocks at start, incremented once at the end
__device__ int g_epoch;

// ------- single fused kernel: GEMM + softmax + scatter + transpose ---------
__global__ __launch_bounds__(NTHREADS, 2)
void lss_fused_kernel(const float* __restrict__ x,
                      const float* __restrict__ rots,
                      const float* __restrict__ trans,
                      const float* __restrict__ intrins,
                      const float* __restrict__ depth_w,
                      const float* __restrict__ depth_b,
                      float* __restrict__ out)
{
    __shared__ __align__(16) float smem[SMEM_FLOATS];
    __shared__ float comb[9];
    __shared__ float tr[3];
    __shared__ int   s_fast;
    __shared__ int   s_ep;
    __shared__ int   s_tgt1;

    const int cam = blockIdx.y;             // 0..11
    const int b   = cam / N_;
    const int w0  = blockIdx.x * WCOLS;     // image-column pair start
    const int tid = threadIdx.x;
    const int tm  = tid >> 3;               // 0..31 -> 4 M-rows (2 even pairs)
    const int tn  = tid & 7;                // 0..7  -> 4 pixels
    const int bid = blockIdx.y * gridDim.x + blockIdx.x;

    // --- epoch read + geometry setup (thread 0) ---
    if (tid == 0) {
        s_ep = *(volatile int*)&g_epoch;    // stable: writer runs post-barrier

        const float* R = rots    + cam * 9;
        const float* K = intrins + cam * 9;
        float a = K[0], bb = K[1], c = K[2];
        float d = K[3], e  = K[4], f = K[5];
        float g = K[6], h  = K[7], i = K[8];
        float A  = e * i - f * h;
        float Bv = -(d * i - f * g);
        float Cv = d * h - e * g;
        float id = 1.0f / (a * A + bb * Bv + c * Cv);
        float inv[9];
        inv[0] = A * id;  inv[1] = (c * h - bb * i) * id; inv[2] = (bb * f - c * e) * id;
        inv[3] = Bv * id; inv[4] = (a * i - c * g) * id;  inv[5] = (c * d - a * f) * id;
        inv[6] = Cv * id; inv[7] = (bb * g - a * h) * id; inv[8] = (a * e - bb * d) * id;
        #pragma unroll
        for (int r = 0; r < 3; r++)
            #pragma unroll
            for (int col = 0; col < 3; col++)
                comb[r * 3 + col] = R[r * 3 + 0] * inv[0 + col]
                                  + R[r * 3 + 1] * inv[3 + col]
                                  + R[r * 3 + 2] * inv[6 + col];
        tr[0] = trans[cam * 3 + 0];
        tr[1] = trans[cam * 3 + 1];
        tr[2] = trans[cam * 3 + 2];
        // fast path: gx, gy independent of image row (exact zeros)
        s_fast = (comb[1] == 0.0f) && (comb[4] == 0.0f);
    }

    // --- phase 1: feat = W @ x, FFMA2, double-buffered smem chunks ---
    ull acc[2][4];                           // [M-pair][pixel]
    #pragma unroll
    for (int i4 = 0; i4 < 2; i4++)
        #pragma unroll
        for (int j = 0; j < 4; j++) acc[i4][j] = 0ull;

    const float* xcam = x + (size_t)cam * CAM_C * HW;

    float wreg[16];   // BM*BK/NTHREADS
    float xreg[4];    // BK*BN/NTHREADS

    // prologue: load chunk 0 into registers, publish to buf0
    #pragma unroll
    for (int it = 0; it < 16; it++) {
        int idx = it * NTHREADS + tid;
        int m   = idx >> 5;
        int kk  = idx & 31;
        wreg[it] = (m < M_FEAT) ? depth_w[m * CAM_C + kk] : 0.f;
    }
    #pragma unroll
    for (int it = 0; it < 4; it++) {
        int idx = it * NTHREADS + tid;
        int kk  = idx >> 5;
        int sub = idx & 31;
        int wl  = sub & 1;
        int h   = sub >> 1;
        xreg[it] = xcam[(size_t)kk * HW + h * FW + w0 + wl];
    }
    {
        float* Ws0 = smem;
        float* Xs0 = smem + BK * WS_STRIDE;
        #pragma unroll
        for (int it = 0; it < 16; it++) {
            int idx = it * NTHREADS + tid;
            int m   = idx >> 5;
            int kk  = idx & 31;
            Ws0[kk * WS_STRIDE + m] = wreg[it];
        }
        #pragma unroll
        for (int it = 0; it < 4; it++) {
            int idx = it * NTHREADS + tid;
            int kk  = idx >> 5;
            int sub = idx & 31;
            int wl  = sub & 1;
            int h   = sub >> 1;
            Xs0[kk * XS_STRIDE + wl * 16 + h] = xreg[it];
        }
    }
    // prefetch chunk 1 into registers while buf0 publishes
    #pragma unroll
    for (int it = 0; it < 16; it++) {
        int idx = it * NTHREADS + tid;
        int m   = idx >> 5;
        int kk  = idx & 31;
        wreg[it] = (m < M_FEAT) ? depth_w[m * CAM_C + BK + kk] : 0.f;
    }
    #pragma unroll
    for (int it = 0; it < 4; it++) {
        int idx = it * NTHREADS + tid;
        int kk  = idx >> 5;
        int sub = idx & 31;
        int wl  = sub & 1;
        int h   = sub >> 1;
        xreg[it] = xcam[(size_t)(BK + kk) * HW + h * FW + w0 + wl];
    }
    __syncthreads();   // buf0 visible

    for (int c = 0; c < NCHUNK; c++) {
        const float* Wsb = smem + (c & 1) * BUF_FLOATS;
        const float* Xsb = Wsb + BK * WS_STRIDE;

        // compute chunk c: 2 LDS.64 (W) + 1 LDS.128 (X) per kk
        #pragma unroll 4
        for (int kk = 0; kk < BK; kk++) {
            ull wp[2];
            #pragma unroll
            for (int i4 = 0; i4 < 2; i4++)
                wp[i4] = *(const ull*)&Wsb[kk * WS_STRIDE + tm * 4 + 2 * i4];
            float4 xv = *(const float4*)&Xsb[kk * XS_STRIDE + tn * 4];
            ull xd[4];
            asm("mov.b64 %0, {%1, %1};" : "=l"(xd[0]) : "f"(xv.x));
            asm("mov.b64 %0, {%1, %1};" : "=l"(xd[1]) : "f"(xv.y));
            asm("mov.b64 %0, {%1, %1};" : "=l"(xd[2]) : "f"(xv.z));
            asm("mov.b64 %0, {%1, %1};" : "=l"(xd[3]) : "f"(xv.w));
            #pragma unroll
            for (int i4 = 0; i4 < 2; i4++)
                #pragma unroll
                for (int j = 0; j < 4; j++)
                    asm("fma.rn.f32x2 %0, %1, %2, %0;"
                        : "+l"(acc[i4][j]) : "l"(wp[i4]), "l"(xd[j]));
        }

        if (c + 1 < NCHUNK) {
            // publish prefetched chunk c+1 into the OTHER buffer (disjoint
            // from buf[c&1] that straggler warps may still be reading)
            float* Wn = smem + ((c + 1) & 1) * BUF_FLOATS;
            float* Xn = Wn + BK * WS_STRIDE;
            #pragma unroll
            for (int it = 0; it < 16; it++) {
                int idx = it * NTHREADS + tid;
                int m   = idx >> 5;
                int kk  = idx & 31;
                Wn[kk * WS_STRIDE + m] = wreg[it];
            }
            #pragma unroll
            for (int it = 0; it < 4; it++) {
                int idx = it * NTHREADS + tid;
                int kk  = idx >> 5;
                int sub = idx & 31;
                int wl  = sub & 1;
                int h   = sub >> 1;
                Xn[kk * XS_STRIDE + wl * 16 + h] = xreg[it];
            }
            // prefetch chunk c+2 into registers
            if (c + 2 < NCHUNK) {
                int kc = (c + 2) * BK;
                #pragma unroll
                for (int it = 0; it < 16; it++) {
                    int idx = it * NTHREADS + tid;
                    int m   = idx >> 5;
                    int kk  = idx & 31;
                    wreg[it] = (m < M_FEAT) ? depth_w[m * CAM_C + kc + kk] : 0.f;
                }
                #pragma unroll
                for (int it = 0; it < 4; it++) {
                    int idx = it * NTHREADS + tid;
                    int kk  = idx >> 5;
                    int sub = idx & 31;
                    int wl  = sub & 1;
                    int h   = sub >> 1;
                    xreg[it] = xcam[(size_t)(kc + kk) * HW + h * FW + w0 + wl];
                }
            }
            __syncthreads();   // single sync per chunk
        }
    }
    // NOTE: no sync needed here — phase 2 writes only smem[0..4128) (buf0
    // sub-region), disjoint from buf1 (offset >= BUF_FLOATS) that straggler
    // warps may still be reading for chunk 7.

    // --- phase 2: unpack accs (+bias) into depthS / ctxS ---
    float* depthS = smem;                     // [np][61]
    float* ctxS   = smem + BN * DS_STRIDE;    // [np][68]

    #pragma unroll
    for (int i4 = 0; i4 < 2; i4++) {
        int m0 = tm * 4 + 2 * i4;
        float b0 = (m0     < M_FEAT) ? depth_b[m0]     : 0.f;
        float b1 = (m0 + 1 < M_FEAT) ? depth_b[m0 + 1] : 0.f;
        #pragma unroll
        for (int j = 0; j < 4; j++) {
            float lo, hi;
            asm("mov.b64 {%0, %1}, %2;" : "=f"(lo), "=f"(hi) : "l"(acc[i4][j]));
            int pix = tn * 4 + j;
            float v0 = lo + b0, v1 = hi + b1;
            if (m0 < D_BINS)       depthS[pix * DS_STRIDE + m0] = v0;
            else if (m0 < M_FEAT)  ctxS[pix * CS_STRIDE + (m0 - D_BINS)] = v0;
            int m1 = m0 + 1;
            if (m1 < D_BINS)       depthS[pix * DS_STRIDE + m1] = v1;
            else if (m1 < M_FEAT)  ctxS[pix * CS_STRIDE + (m1 - D_BINS)] = v1;
        }
    }
    __syncthreads();

    const float c00 = comb[0], c01 = comb[1], c02 = comb[2];
    const float c10 = comb[3], c11 = comb[4], c12 = comb[5];
    const float c20 = comb[6], c21 = comb[7], c22 = comb[8];
    const float t0 = tr[0], t1 = tr[1], t2 = tr[2];
    const float xstep = 703.0f / 43.0f;
    const float ystep = 255.0f / 15.0f;
    const int   fast  = s_fast;
    const int   ep    = s_ep;

    // --- softmax: 8 lanes per pixel, shfl reductions; zero z-invalid bins ---
    {
        int pix = tid >> 3;          // 0..31
        int sub = tid & 7;           // 0..7
        float* row = depthS + pix * DS_STRIDE;

        float mx = -1e30f;
        for (int d = sub; d < D_BINS; d += 8) mx = fmaxf(mx, row[d]);
        #pragma unroll
        for (int o = 1; o < 8; o <<= 1)
            mx = fmaxf(mx, __shfl_xor_sync(0xffffffffu, mx, o));

        float s = 0.f;
        for (int d = sub; d < D_BINS; d += 8) {
            float e = __expf(row[d] - mx);
            row[d] = e;
            s += e;
        }
        #pragma unroll
        for (int o = 1; o < 8; o <<= 1)
            s += __shfl_xor_sync(0xffffffffu, s, o);
        float invs = 1.0f / s;

        if (fast) {
            int wl = pix >> 4, h = pix & 15;
            float xim = (float)(w0 + wl) * xstep;
            float yim = (float)h * ystep;
            for (int d = sub; d < D_BINS; d += 8) {
                float ds = 1.0f + (float)d;
                float gz = c20 * (xim * ds) + c21 * (yim * ds) + c22 * ds + t2;
                int cz = (int)floorf((gz + 10.0f) / 20.0f);
                row[d] = (cz == 0) ? row[d] * invs : 0.f;
            }
        } else {
            for (int d = sub; d < D_BINS; d += 8) row[d] *= invs;
        }
    }
    __syncthreads();   // publish softmax; active buffer is pre-zeroed

    float* scrA = g_scratch + (size_t)(ep & 1) * SCR_SZ;          // active
    float* scrB = g_scratch + (size_t)((ep + 1) & 1) * SCR_SZ;    // to zero
    float* base = scrA + (size_t)b * NCELL * OUT_C;

    if (fast) {
        // --- fast combine+scatter: warp = (wl, 16-depth chunk);
        //     lane = (dloc, channel-half). ctx broadcast, accs in registers.
        const int warp  = tid >> 5;           // 0..7
        const int lane  = tid & 31;
        const int wl    = warp & 1;
        const int d0    = (warp >> 1) * 16;   // 0,16,32,48
        const int dloc  = lane >> 1;          // 0..15
        const int d     = d0 + dloc;
        const int chalf = lane & 1;           // channels chalf*32 .. +31
        const bool dok  = (d < D_BINS);

        float ds  = 1.0f + (float)d;
        float xim = (float)(w0 + wl) * xstep;
        float gx = c00 * (xim * ds) + c02 * ds + t0;   // c01 exactly 0
        float gy = c10 * (xim * ds) + c12 * ds + t1;   // c11 exactly 0
        int cx = (int)floorf((gx + 51.2f) / 0.8f);
        int cy = (int)floorf((gy + 51.2f) / 0.8f);
        bool ok = dok && ((unsigned)cx < (unsigned)NX) && ((unsigned)cy < (unsigned)NY);

        ull v[16];                              // 8 float4 accumulators
        #pragma unroll
        for (int j = 0; j < 16; j++) v[j] = 0ull;
        float dwsum = 0.f;

        const float* drow0 = depthS + (wl * 16) * DS_STRIDE;
        const float* crow0 = ctxS   + (wl * 16) * CS_STRIDE + chalf * 32;

        #pragma unroll
        for (int h = 0; h < 16; h++) {
            float dw = dok ? drow0[h * DS_STRIDE + d] : 0.f;
            dwsum += dw;
            ull dw2; asm("mov.b64 %0, {%1, %1};" : "=l"(dw2) : "f"(dw));
            const float* cr = crow0 + h * CS_STRIDE;
            #pragma unroll
            for (int q = 0; q < 8; q++) {
                float4 cc = *(const float4*)(cr + q * 4);   // warp-broadcast
                ull lo, hi;
                asm("mov.b64 %0, {%1, %2};" : "=l"(lo) : "f"(cc.x), "f"(cc.y));
                asm("mov.b64 %0, {%1, %2};" : "=l"(hi) : "f"(cc.z), "f"(cc.w));
                asm("fma.rn.f32x2 %0, %1, %2, %0;" : "+l"(v[2*q  ]) : "l"(lo), "l"(dw2));
                asm("fma.rn.f32x2 %0, %1, %2, %0;" : "+l"(v[2*q+1]) : "l"(hi), "l"(dw2));
            }
        }

        if (ok && dwsum != 0.f) {
            float* dst = base + ((size_t)cy * NX + cx) * OUT_C + chalf * 32;
            #pragma unroll
            for (int q = 0; q < 8; q++) {
                float f0, f1, f2, f3;
                asm("mov.b64 {%0, %1}, %2;" : "=f"(f0), "=f"(f1) : "l"(v[2*q  ]));
                asm("mov.b64 {%0, %1}, %2;" : "=f"(f2), "=f"(f3) : "l"(v[2*q+1]));
                asm volatile("red.global.add.v4.f32 [%0], {%1, %2, %3, %4};"
                             :: "l"(dst + q * 4),
                                "f"(f0), "f"(f1), "f"(f2), "f"(f3) : "memory");
            }
        }
    } else {
        // --- generic fallback: per-point scatter (any geometry) ---
        for (int idx = tid; idx < BN * D_BINS; idx += NTHREADS) {
            int np = idx / D_BINS;
            int d  = idx - np * D_BINS;
            int wl = np >> 4, h = np & 15;
            float ds  = 1.0f + (float)d;
            float xim = (float)(w0 + wl) * xstep;
            float yim = (float)h * ystep;
            float px = xim * ds, py = yim * ds, pz = ds;
            float gx = c00 * px + c01 * py + c02 * pz + t0;
            float gy = c10 * px + c11 * py + c12 * pz + t1;
            float gz = c20 * px + c21 * py + c22 * pz + t2;
            int cx = (int)floorf((gx + 51.2f) / 0.8f);
            int cy = (int)floorf((gy + 51.2f) / 0.8f);
            int cz = (int)floorf((gz + 10.0f) / 20.0f);
            if (((unsigned)cx < (unsigned)NX) && ((unsigned)cy < (unsigned)NY) && cz == 0) {
                float dwgt = depthS[np * DS_STRIDE + d];
                float* dst = base + ((size_t)cy * NX + cx) * OUT_C;
                const float4* cv = (const float4*)(ctxS + np * CS_STRIDE);
                #pragma unroll
                for (int c4 = 0; c4 < OUT_C / 4; c4++) {
                    float4 v = cv[c4];
                    asm volatile("red.global.add.v4.f32 [%0], {%1, %2, %3, %4};"
                                 :: "l"(dst + c4 * 4),
                                    "f"(v.x * dwgt), "f"(v.y * dwgt),
                                    "f"(v.z * dwgt), "f"(v.w * dwgt) : "memory");
                }
            }
        }
    }

    // --- grid barrier: take ticket, zero the OTHER buffer while waiting ---
    __threadfence();
    if (tid == 0) {
        int t = atomicAdd(&g_cnt_scat, 1);
        s_tgt1 = t - (t % NBLOCKS) + NBLOCKS;
    }
    __syncthreads();

    // zero next launch's buffer (cold lines, overlaps stragglers + red drain)
    {
        const int n4 = SCR_SZ / 4;                         // 524288 float4
        const int chunk = (n4 + NBLOCKS - 1) / NBLOCKS;
        int s = bid * chunk;
        int e = s + chunk; if (e > n4) e = n4;
        float4* p = (float4*)scrB;
        const float4 z4 = make_float4(0.f, 0.f, 0.f, 0.f);
        for (int i = s + tid; i < e; i += NTHREADS)
            p[i] = z4;
    }
    __syncthreads();

    if (tid == 0) {
        while (*(volatile int*)&g_cnt_scat < s_tgt1) __nanosleep(64);
    }
    __syncthreads();
    __threadfence();   // acquire: scratch reads below must not be hoisted

    // --- phase 4: transpose (B, cell, C) -> (B, C, cell), READ-ONLY ---
    {
        float (*tile)[65] = (float (*)[65])smem;   // 64 x 65 = 4160 floats, fits
        for (int t = bid; t < NTILES; t += NBLOCKS) {
            int bz    = t >> 8;             // t / 256
            int cell0 = (t & 255) * 64;
            __syncthreads();                // smem reuse across iterations
            #pragma unroll
            for (int i = 0; i < 4; i++) {
                int idx  = i * NTHREADS + tid;      // 0..1023
                int cell = idx >> 4;
                int c4   = idx & 15;
                float4 v = *(const float4*)&scrA[
                    ((size_t)bz * NCELL + cell0 + cell) * OUT_C + c4 * 4];
                tile[c4 * 4 + 0][cell] = v.x;
                tile[c4 * 4 + 1][cell] = v.y;
                tile[c4 * 4 + 2][cell] = v.z;
                tile[c4 * 4 + 3][cell] = v.w;
            }
            __syncthreads();
            #pragma unroll
            for (int i = 0; i < 4; i++) {
                int idx = i * NTHREADS + tid;
                int ch  = idx >> 4;
                int seg = idx & 15;
                float4 v = make_float4(tile[ch][seg * 4 + 0], tile[ch][seg * 4 + 1],
                                       tile[ch][seg * 4 + 2], tile[ch][seg * 4 + 3]);
                *(float4*)&out[((size_t)(bz * OUT_C + ch)) * NCELL + cell0 + seg * 4] = v;
            }
        }
    }

    // --- advance epoch (exactly one writer; all blocks have long since read) ---
    if (bid == 0 && tid == 0)
        *(volatile int*)&g_epoch = ep + 1;
}

// ---------------- launch ----------------
extern "C" void kernel_launch(void* const* d_in, const int* in_sizes, int n_in,
                              void* d_out, int out_size)
{
    const float* x       = (const float*)d_in[0];
    const float* rots    = (const float*)d_in[1];
    const float* trans   = (const float*)d_in[2];
    const float* intrins = (const float*)d_in[3];
    const float* depth_w = (const float*)d_in[4];
    const float* depth_b = (const float*)d_in[5];
    float* out = (float*)d_out;

    // single fused kernel: GEMM + softmax + scatter + transpose (ping-pong)
    dim3 grid(FW / WCOLS, CAMS);   // (22, 12) = 264 blocks, occ 2 -> 1 wave
    lss_fused_kernel<<<grid, NTHREADS>>>(x, rots, trans, intrins,
                                         depth_w, depth_b, out);
    (void)in_sizes; (void)n_in; (void)out_size;
}